// round 1
// baseline (speedup 1.0000x reference)
#include <cuda_runtime.h>
#include <math.h>

#define NN   50000
#define EE   800000
#define ET   (NN + EE)     // 850000 edges incl. self loops
#define DHID 128
#define DOUT 64

// ---------------- device scratch (static, no allocation) ----------------
__device__ int   g_cnt[NN];
__device__ float g_sumw[NN];
__device__ float g_loopw[NN];
__device__ int   g_rowptr[NN + 1];
__device__ int   g_cursor[NN];
__device__ int   g_esrc[ET];
__device__ float g_ew[ET];
__device__ float g_xl[NN * DHID];
__device__ float g_xr[NN * DHID];
__device__ float g_h [NN * DHID];

// ---------------- helpers ----------------
__device__ __forceinline__ unsigned long long fma2(unsigned long long a,
                                                   unsigned long long b,
                                                   unsigned long long c) {
    unsigned long long d;
    asm("fma.rn.f32x2 %0, %1, %2, %3;" : "=l"(d) : "l"(a), "l"(b), "l"(c));
    return d;
}
__device__ __forceinline__ unsigned long long pack2(float v) {
    unsigned long long r;
    unsigned u = __float_as_uint(v);
    asm("mov.b64 %0, {%1, %1};" : "=l"(r) : "r"(u));
    return r;
}
__device__ __forceinline__ float lo2(unsigned long long u) {
    return __uint_as_float((unsigned)u);
}
__device__ __forceinline__ float hi2(unsigned long long u) {
    return __uint_as_float((unsigned)(u >> 32));
}

// ---------------- CSR build ----------------
__global__ void k_zero() {
    int i = blockIdx.x * blockDim.x + threadIdx.x;
    if (i < NN) { g_cnt[i] = 0; g_sumw[i] = 0.f; g_cursor[i] = 0; }
}

__global__ void k_hist(const int* __restrict__ ei, const float* __restrict__ ew) {
    int e = blockIdx.x * blockDim.x + threadIdx.x;
    if (e < EE) {
        int d = ei[EE + e];
        atomicAdd(&g_cnt[d], 1);
        atomicAdd(&g_sumw[d], ew[e]);
    }
}

// single block, 1024 threads: exclusive scan of (cnt+1), plus loop weights
__global__ void k_scan() {
    __shared__ int warp_tot[32];
    int tid = threadIdx.x, lane = tid & 31, wid = tid >> 5;
    int offset = 0;
    for (int base = 0; base < NN; base += 1024) {
        int v = base + tid;
        int d = 0;
        if (v < NN) {
            int c = g_cnt[v];
            g_loopw[v] = g_sumw[v] / fmaxf((float)c, 1.0f);
            d = c + 1;                       // +1 self loop
        }
        int x = d;
        #pragma unroll
        for (int o = 1; o < 32; o <<= 1) {
            int y = __shfl_up_sync(0xffffffffu, x, o);
            if (lane >= o) x += y;
        }
        if (lane == 31) warp_tot[wid] = x;
        __syncthreads();
        if (wid == 0) {
            int t = warp_tot[lane];
            #pragma unroll
            for (int o = 1; o < 32; o <<= 1) {
                int y = __shfl_up_sync(0xffffffffu, t, o);
                if (lane >= o) t += y;
            }
            warp_tot[lane] = t;
        }
        __syncthreads();
        int pre   = (wid > 0) ? warp_tot[wid - 1] : 0;
        int total = warp_tot[31];
        if (v < NN) g_rowptr[v] = offset + pre + x - d;   // exclusive
        offset += total;
        __syncthreads();
    }
    if (tid == 0) g_rowptr[NN] = offset;
}

__global__ void k_scatter(const int* __restrict__ ei, const float* __restrict__ ew) {
    int i = blockIdx.x * blockDim.x + threadIdx.x;
    if (i < EE) {
        int s = ei[i], d = ei[EE + i];
        int p = atomicAdd(&g_cursor[d], 1);
        int o = g_rowptr[d] + 1 + p;     // slot 0 reserved for self loop
        g_esrc[o] = s;
        g_ew[o]   = ew[i];
    } else if (i < ET) {
        int v = i - EE;
        int o = g_rowptr[v];
        g_esrc[o] = v;
        g_ew[o]   = g_loopw[v];
    }
}

// ---------------- dual GEMM: outl = X@Wl+bl, outr = X@Wr+br ----------------
// KIN = 128 always.  512 threads, 64 nodes/block, 4 nodes/warp.
template <int KOUT>
__global__ void k_gemm_dual(const float* __restrict__ X,
                            const float* __restrict__ Wl, const float* __restrict__ bl,
                            const float* __restrict__ Wr, const float* __restrict__ br,
                            float* __restrict__ outl, float* __restrict__ outr) {
    constexpr int KIN = 128;
    constexpr int NB  = 64;
    constexpr int CPL = KOUT / 32;       // cols per lane: 4 or 2
    constexpr int NPW = 4;               // nodes per warp
    constexpr int PP  = CPL / 2;         // f32x2 pairs per lane

    extern __shared__ float smem[];
    float* sWl = smem;                   // KIN*KOUT
    float* sWr = sWl + KIN * KOUT;
    float* sX  = sWr + KIN * KOUT;       // NB*KIN

    int tid = threadIdx.x;
    for (int i = tid * 4; i < KIN * KOUT; i += blockDim.x * 4) {
        *(float4*)&sWl[i] = *(const float4*)&Wl[i];
        *(float4*)&sWr[i] = *(const float4*)&Wr[i];
    }
    int nbase = blockIdx.x * NB;
    for (int i = tid * 4; i < NB * KIN; i += blockDim.x * 4) {
        int n = nbase + i / KIN;
        float4 v = make_float4(0.f, 0.f, 0.f, 0.f);
        if (n < NN) v = *(const float4*)&X[(size_t)n * KIN + (i % KIN)];
        *(float4*)&sX[i] = v;
    }
    __syncthreads();

    int wid = tid >> 5, lane = tid & 31;
    int wn  = wid * NPW;
    int c0  = lane * CPL;

    unsigned long long accl[NPW][PP], accr[NPW][PP];
    #pragma unroll
    for (int n = 0; n < NPW; n++)
        #pragma unroll
        for (int p = 0; p < PP; p++) { accl[n][p] = 0ull; accr[n][p] = 0ull; }

    #pragma unroll 4
    for (int k = 0; k < KIN; k++) {
        unsigned long long wl[PP], wr[PP];
        #pragma unroll
        for (int p = 0; p < PP; p++) {
            wl[p] = *(const unsigned long long*)&sWl[k * KOUT + c0 + 2 * p];
            wr[p] = *(const unsigned long long*)&sWr[k * KOUT + c0 + 2 * p];
        }
        #pragma unroll
        for (int n = 0; n < NPW; n++) {
            unsigned long long xx = pack2(sX[(wn + n) * KIN + k]);
            #pragma unroll
            for (int p = 0; p < PP; p++) {
                accl[n][p] = fma2(xx, wl[p], accl[n][p]);
                accr[n][p] = fma2(xx, wr[p], accr[n][p]);
            }
        }
    }

    #pragma unroll
    for (int n = 0; n < NPW; n++) {
        int node = nbase + wn + n;
        if (node >= NN) break;
        #pragma unroll
        for (int p = 0; p < PP; p++) {
            int c = c0 + 2 * p;
            outl[(size_t)node * KOUT + c]     = lo2(accl[n][p]) + bl[c];
            outl[(size_t)node * KOUT + c + 1] = hi2(accl[n][p]) + bl[c + 1];
            outr[(size_t)node * KOUT + c]     = lo2(accr[n][p]) + br[c];
            outr[(size_t)node * KOUT + c + 1] = hi2(accr[n][p]) + br[c + 1];
        }
    }
}

// ---------------- edge phase: warp per node, online softmax ----------------
// D = H*C channels; head of a lane is lane/(32/H); channels are contiguous per head.
template <int D, int H, bool DO_ELU>
__global__ void k_edge(const float* __restrict__ We, const float* __restrict__ att,
                       const float* __restrict__ bias, float* __restrict__ out) {
    constexpr int CPL = D / 32;
    constexpr int G   = 32 / H;          // lanes per head group
    int gw   = (blockIdx.x * blockDim.x + threadIdx.x) >> 5;
    int lane = threadIdx.x & 31;
    if (gw >= NN) return;
    int v  = gw;
    int c0 = lane * CPL;

    float b[CPL], we[CPL], at[CPL], acc[CPL];
    #pragma unroll
    for (int j = 0; j < CPL; j++) {
        b[j]   = g_xr[(size_t)v * D + c0 + j];
        we[j]  = We[c0 + j];
        at[j]  = att[c0 + j];
        acc[j] = 0.f;
    }

    float m = -1e30f, s = 0.f;
    int beg = g_rowptr[v], end = g_rowptr[v + 1];

    // prefetch first edge
    int   psrc = g_esrc[beg];
    float pw   = g_ew[beg];
    float an[CPL];
    if (CPL == 4) {
        float4 t = *(const float4*)&g_xl[(size_t)psrc * D + c0];
        an[0] = t.x; an[1] = t.y; an[2] = t.z; an[3] = t.w;
    } else {
        float2 t = *(const float2*)&g_xl[(size_t)psrc * D + c0];
        an[0] = t.x; an[1] = t.y;
    }

    for (int i = beg; i < end; i++) {
        float a[CPL];
        #pragma unroll
        for (int j = 0; j < CPL; j++) a[j] = an[j];
        float wcur = pw;

        if (i + 1 < end) {
            psrc = g_esrc[i + 1];
            pw   = g_ew[i + 1];
            if (CPL == 4) {
                float4 t = *(const float4*)&g_xl[(size_t)psrc * D + c0];
                an[0] = t.x; an[1] = t.y; an[2] = t.z; an[3] = t.w;
            } else {
                float2 t = *(const float2*)&g_xl[(size_t)psrc * D + c0];
                an[0] = t.x; an[1] = t.y;
            }
        }

        float t = 0.f;
        #pragma unroll
        for (int j = 0; j < CPL; j++) {
            float e = a[j] + b[j] + wcur * we[j];
            e = e > 0.f ? e : 0.2f * e;          // leaky relu
            t = fmaf(e, at[j], t);
        }
        #pragma unroll
        for (int o = 1; o < G; o <<= 1) t += __shfl_xor_sync(0xffffffffu, t, o);

        float nm = fmaxf(m, t);
        float f  = __expf(m - nm);
        float p  = __expf(t - nm);
        s = s * f + p;
        #pragma unroll
        for (int j = 0; j < CPL; j++) acc[j] = fmaf(acc[j], f, p * a[j]);
        m = nm;
    }

    float inv = 1.f / (s + 1e-16f);
    #pragma unroll
    for (int j = 0; j < CPL; j++) {
        float o = fmaf(acc[j], inv, bias[c0 + j]);
        if (DO_ELU) o = o > 0.f ? o : (expf(o) - 1.f);
        out[(size_t)v * D + c0 + j] = o;
    }
}

// ---------------- launch ----------------
extern "C" void kernel_launch(void* const* d_in, const int* in_sizes, int n_in,
                              void* d_out, int out_size) {
    (void)in_sizes; (void)n_in; (void)out_size;
    const float* x    = (const float*)d_in[0];
    const int*   ei   = (const int*)  d_in[1];
    const float* ew   = (const float*)d_in[2];
    const float* Wl0  = (const float*)d_in[3];
    const float* bl0  = (const float*)d_in[4];
    const float* Wr0  = (const float*)d_in[5];
    const float* br0  = (const float*)d_in[6];
    const float* We0  = (const float*)d_in[7];
    const float* att0 = (const float*)d_in[8];
    const float* bias0= (const float*)d_in[9];
    const float* Wl1  = (const float*)d_in[10];
    const float* bl1  = (const float*)d_in[11];
    const float* Wr1  = (const float*)d_in[12];
    const float* br1  = (const float*)d_in[13];
    const float* We1  = (const float*)d_in[14];
    const float* att1 = (const float*)d_in[15];
    const float* bias1= (const float*)d_in[16];
    const float* Wl2  = (const float*)d_in[17];
    const float* bl2  = (const float*)d_in[18];
    const float* Wr2  = (const float*)d_in[19];
    const float* br2  = (const float*)d_in[20];
    const float* We2  = (const float*)d_in[21];
    const float* att2 = (const float*)d_in[22];
    const float* bias2= (const float*)d_in[23];
    float* out = (float*)d_out;

    float *p_xl, *p_xr, *p_h;
    cudaGetSymbolAddress((void**)&p_xl, g_xl);
    cudaGetSymbolAddress((void**)&p_xr, g_xr);
    cudaGetSymbolAddress((void**)&p_h,  g_h);

    const int SMEM128 = (128 * 128 * 2 + 64 * 128) * (int)sizeof(float); // 160 KB
    const int SMEM64  = (128 * 64  * 2 + 64 * 128) * (int)sizeof(float); //  96 KB
    cudaFuncSetAttribute(k_gemm_dual<128>, cudaFuncAttributeMaxDynamicSharedMemorySize, SMEM128);
    cudaFuncSetAttribute(k_gemm_dual<64>,  cudaFuncAttributeMaxDynamicSharedMemorySize, SMEM64);

    // CSR build (identical across layers)
    k_zero   <<<(NN + 255) / 256, 256>>>();
    k_hist   <<<(EE + 255) / 256, 256>>>(ei, ew);
    k_scan   <<<1, 1024>>>();
    k_scatter<<<(ET + 255) / 256, 256>>>(ei, ew);

    const int GEMM_GRID = (NN + 63) / 64;
    const int EDGE_GRID = (NN + 7) / 8;   // 8 warps / 256-thread block

    // layer 0: x -> g_h (ELU)
    k_gemm_dual<128><<<GEMM_GRID, 512, SMEM128>>>(x, Wl0, bl0, Wr0, br0, p_xl, p_xr);
    k_edge<128, 4, true><<<EDGE_GRID, 256>>>(We0, att0, bias0, p_h);

    // layer 1: g_h -> g_h (ELU)
    k_gemm_dual<128><<<GEMM_GRID, 512, SMEM128>>>(p_h, Wl1, bl1, Wr1, br1, p_xl, p_xr);
    k_edge<128, 4, true><<<EDGE_GRID, 256>>>(We1, att1, bias1, p_h);

    // layer 2: g_h -> out (no ELU, H=1, C=64)
    k_gemm_dual<64><<<GEMM_GRID, 512, SMEM64>>>(p_h, Wl2, bl2, Wr2, br2, p_xl, p_xr);
    k_edge<64, 1, false><<<EDGE_GRID, 256>>>(We2, att2, bias2, out);
}